// round 6
// baseline (speedup 1.0000x reference)
#include <cuda_runtime.h>
#include <cuda_bf16.h>
#include <math.h>

// BboxSemanticAtt: out[b,y,x] = sigmoid( sum_i c_i * [y1<=y<y2][x1<=x<x2] )
// preds: [B, 256, 5] f32; out: [B, 512, 512] f32.
//
// Warp owns a 4-row chunk (8192 chunks -> ~55 warps/SM). Build first row via
// smem corner-scatter + stride-17 scan, keep row values in registers (v holds
// g/2; confidences pre-halved), update incrementally per row from per-row
// event buckets read via broadcast LDS (no ballot/shfl). Sigmoid = 1 MUFU:
// sigma(g) = 0.5*tanh(g/2)+0.5.

#define FEAT   512
#define NBOX   256
#define NWARPS 4
#define CHUNK  4
#define ROWS_PER_BLOCK (NWARPS * CHUNK)   // 16
#define ROW_PAD 544                        // 512 + 512/16 padding slots
#define EVCAP  8                           // bucket capacity per row

__global__ __launch_bounds__(128, 12)
void bbox_att_kernel(const float* __restrict__ preds,
                     float* __restrict__ out,
                     int blocksPerBatch)
{
    __shared__ int   sx12[NBOX];                     // x1 | (x2 << 16)
    __shared__ int   sy12[NBOX];                     // y1 | (y2 << 16), 0 if invalid
    __shared__ float sc  [NBOX];                     // 0.5 * conf
    __shared__ float rows[NWARPS][ROW_PAD];          // first-row build scratch
    __shared__ uint2 ev  [ROWS_PER_BLOCK][EVCAP];    // per-row event buckets
    __shared__ int   evn [ROWS_PER_BLOCK];
    __shared__ unsigned rowMaskS, ovMaskS;

    const int b       = blockIdx.x / blocksPerBatch;
    const int rowBase = (blockIdx.x % blocksPerBatch) * ROWS_PER_BLOCK;
    const int tid     = threadIdx.x;
    const int warp    = tid >> 5;
    const int lane    = tid & 31;

    if (tid < ROWS_PER_BLOCK) evn[tid] = 0;
    if (tid == 0) { rowMaskS = 0u; ovMaskS = 0u; }
    __syncthreads();

    // ---- load + quantize boxes; bucket in-block enter/exit events ----
    for (int i = tid; i < NBOX; i += 128) {
        const float* p = preds + ((size_t)b * NBOX + i) * 5;
        float c  = p[0];
        int x1 = min(max((int)floorf(p[1] * 512.0f), 0), FEAT);
        int y1 = min(max((int)floorf(p[2] * 512.0f), 0), FEAT);
        int x2 = min(max((int)floorf(p[3] * 512.0f), 0), FEAT);
        int y2 = min(max((int)floorf(p[4] * 512.0f), 0), FEAT);
        if (!((x2 > x1) && (y2 > y1))) { y1 = 0; y2 = 0; }   // empty y-range
        sx12[i] = x1 | (x2 << 16);
        sy12[i] = y1 | (y2 << 16);
        float hc = 0.5f * c;                                  // pre-halved
        sc[i] = hc;

        unsigned xp = (unsigned)x1 | ((unsigned)x2 << 10);
        int d1 = y1 - rowBase;                                // enter event
        if (d1 > 0 && d1 < ROWS_PER_BLOCK && (d1 & (CHUNK - 1))) {
            atomicOr(&rowMaskS, 1u << d1);
            int e = atomicAdd(&evn[d1], 1);
            if (e < EVCAP) ev[d1][e] = make_uint2(xp, __float_as_uint(hc));
            else           atomicOr(&ovMaskS, 1u << d1);
        }
        int d2 = y2 - rowBase;                                // exit event
        if (d2 > 0 && d2 < ROWS_PER_BLOCK && (d2 & (CHUNK - 1))) {
            atomicOr(&rowMaskS, 1u << d2);
            int e = atomicAdd(&evn[d2], 1);
            if (e < EVCAP) ev[d2][e] = make_uint2(xp, __float_as_uint(-hc));
            else           atomicOr(&ovMaskS, 1u << d2);
        }
    }
    __syncthreads();
    const unsigned rowMask = rowMaskS;
    const unsigned ovMask  = ovMaskS;

    const int y0 = rowBase + warp * CHUNK;
    float* row = rows[warp];

    // ---- zero the build row ----
    #pragma unroll
    for (int i = lane; i < ROW_PAD; i += 32) row[i] = 0.0f;
    __syncwarp();

    // ---- scatter boxes active at y0 (padded index p + p>>4) ----
    #pragma unroll
    for (int i = lane; i < NBOX; i += 32) {
        int y12 = sy12[i];
        int y1 = y12 & 0xFFFF, y2 = y12 >> 16;
        if (y1 <= y0 && y0 < y2) {
            int x12 = sx12[i];
            float hc = sc[i];
            int a1 = x12 & 0xFFFF;
            atomicAdd(&row[a1 + (a1 >> 4)],  hc);
            int a2 = x12 >> 16;
            if (a2 < FEAT) atomicAdd(&row[a2 + (a2 >> 4)], -hc);
        }
    }
    __syncwarp();

    // ---- scan first row into registers (conflict-free: stride 17) ----
    float v[16];
    {
        const int base = lane * 17;
        float run = 0.0f;
        #pragma unroll
        for (int j = 0; j < 16; j++) { run += row[base + j]; v[j] = run; }

        float x = run;
        #pragma unroll
        for (int o = 1; o < 32; o <<= 1) {
            float t = __shfl_up_sync(0xFFFFFFFFu, x, o);
            if (lane >= o) x += t;
        }
        float pre = __shfl_up_sync(0xFFFFFFFFu, x, 1);
        if (lane == 0) pre = 0.0f;
        #pragma unroll
        for (int j = 0; j < 16; j++) v[j] += pre;
    }

    // ---- per-row: sigmoid + store, then apply next row's events ----
    const int s = lane * 16;
    float* dstBase = out + (((size_t)b * FEAT + y0) * FEAT) + s;

    for (int r = 0; r < CHUNK; r++) {
        // sigmoid(2v) = 0.5*tanh(v)+0.5 ; compute+store 4 at a time (low reg pressure)
        float4* dst = (float4*)(dstBase + (size_t)r * FEAT);
        #pragma unroll
        for (int g = 0; g < 4; g++) {
            float4 t4;
            float* tp = (float*)&t4;
            #pragma unroll
            for (int j = 0; j < 4; j++) {
                float t;
                asm("tanh.approx.f32 %0, %1;" : "=f"(t) : "f"(v[g * 4 + j]));
                tp[j] = fmaf(0.5f, t, 0.5f);
            }
            dst[g] = t4;
        }

        if (r + 1 < CHUNK) {
            const int target = warp * CHUNK + r + 1;      // block-row index
            if ((rowMask >> target) & 1u) {
                if (!((ovMask >> target) & 1u)) {
                    // fast path: broadcast-read bucket events (no shfl/ballot)
                    const int n = evn[target];
                    for (int k = 0; k < n; k++) {
                        uint2 e = ev[target][k];
                        int lo = max((int)(e.x & 0x3FF) - s, 0);
                        int hi = min((int)((e.x >> 10) & 0x3FF) - s, 16);
                        float c2 = __uint_as_float(e.y);
                        if (lo < hi) {
                            #pragma unroll
                            for (int j = 0; j < 16; j++)
                                if (j >= lo && j < hi) v[j] += c2;
                        }
                    }
                } else {
                    // rare overflow: broadcast rescan of full box list
                    const int yt = y0 + r + 1;
                    for (int i = 0; i < NBOX; i++) {
                        int y12 = sy12[i];
                        int y1 = y12 & 0xFFFF, y2 = y12 >> 16;
                        bool en = (y1 == yt), ex = (y2 == yt && y2 > y1);
                        if (en || ex) {
                            int x12 = sx12[i];
                            float c2 = en ? sc[i] : -sc[i];
                            int lo = max((x12 & 0xFFFF) - s, 0);
                            int hi = min((x12 >> 16) - s, 16);
                            if (lo < hi) {
                                #pragma unroll
                                for (int j = 0; j < 16; j++)
                                    if (j >= lo && j < hi) v[j] += c2;
                            }
                        }
                    }
                }
            }
        }
    }
}

extern "C" void kernel_launch(void* const* d_in, const int* in_sizes, int n_in,
                              void* d_out, int out_size)
{
    const float* preds = (const float*)d_in[0];
    float* out = (float*)d_out;

    int B = in_sizes[0] / (NBOX * 5);               // 64 for bench shapes
    int blocksPerBatch = FEAT / ROWS_PER_BLOCK;     // 32
    dim3 grid(B * blocksPerBatch);                  // 2048
    dim3 block(128);
    bbox_att_kernel<<<grid, block>>>(preds, out, blocksPerBatch);
}

// round 7
// speedup vs baseline: 1.0718x; 1.0718x over previous
#include <cuda_runtime.h>
#include <cuda_bf16.h>
#include <math.h>

// BboxSemanticAtt: out[b,y,x] = sigmoid( sum_i c_i * [y1<=y<y2][x1<=x<x2] )
// preds: [B, 256, 5] f32; out: [B, 512, 512] f32.
//
// Warp owns an 8-row chunk. Build first row via smem corner-scatter +
// stride-20 padded scan (LDS.128/STS.128, conflict-free), keep row values in
// registers (v = g/2, confidences pre-halved), update per row from per-row
// event buckets via broadcast LDS (no shfl/ballot). Sigmoid = 1 MUFU.TANH.

#define FEAT   512
#define NBOX   256
#define NWARPS 4
#define CHUNK  8
#define ROWS_PER_BLOCK (NWARPS * CHUNK)   // 32
#define ROW_WORDS 644                      // 512 data + 4 pad per 16 (+x2=512 slot)
#define ROW_V4   161                       // ceil(644/4)
#define EVCAP  8                           // bucket capacity per row

// element p -> padded word index
__device__ __forceinline__ int padw(int p) { return p + ((p >> 4) << 2); }

__global__ __launch_bounds__(128, 12)
void bbox_att_kernel(const float* __restrict__ preds,
                     float* __restrict__ out,
                     int blocksPerBatch)
{
    __shared__ uint2 sbox[NBOX];                     // {x1|x2<<16, y1|y2<<16}
    __shared__ float sc  [NBOX];                     // 0.5 * conf
    __shared__ float4 rows4[NWARPS][ROW_V4];         // first-row build scratch
    __shared__ uint2 ev  [ROWS_PER_BLOCK][EVCAP];    // per-row event buckets
    __shared__ int   evn [ROWS_PER_BLOCK];
    __shared__ unsigned rowMaskS, ovMaskS;

    const int b       = blockIdx.x / blocksPerBatch;
    const int rowBase = (blockIdx.x % blocksPerBatch) * ROWS_PER_BLOCK;
    const int tid     = threadIdx.x;
    const int warp    = tid >> 5;
    const int lane    = tid & 31;

    if (tid < ROWS_PER_BLOCK) evn[tid] = 0;
    if (tid == 0) { rowMaskS = 0u; ovMaskS = 0u; }
    __syncthreads();

    // ---- load + quantize boxes; bucket in-block enter/exit events ----
    for (int i = tid; i < NBOX; i += 128) {
        const float* p = preds + ((size_t)b * NBOX + i) * 5;
        float c  = p[0];
        int x1 = min(max((int)floorf(p[1] * 512.0f), 0), FEAT);
        int y1 = min(max((int)floorf(p[2] * 512.0f), 0), FEAT);
        int x2 = min(max((int)floorf(p[3] * 512.0f), 0), FEAT);
        int y2 = min(max((int)floorf(p[4] * 512.0f), 0), FEAT);
        if (!((x2 > x1) && (y2 > y1))) { y1 = 0; y2 = 0; }   // empty y-range
        sbox[i] = make_uint2((unsigned)(x1 | (x2 << 16)),
                             (unsigned)(y1 | (y2 << 16)));
        float hc = 0.5f * c;                                  // pre-halved
        sc[i] = hc;

        unsigned xp = (unsigned)x1 | ((unsigned)x2 << 10);
        int d1 = y1 - rowBase;                                // enter event
        if (d1 > 0 && d1 < ROWS_PER_BLOCK && (d1 & (CHUNK - 1))) {
            atomicOr(&rowMaskS, 1u << d1);
            int e = atomicAdd(&evn[d1], 1);
            if (e < EVCAP) ev[d1][e] = make_uint2(xp, __float_as_uint(hc));
            else           atomicOr(&ovMaskS, 1u << d1);
        }
        int d2 = y2 - rowBase;                                // exit event
        if (d2 > 0 && d2 < ROWS_PER_BLOCK && (d2 & (CHUNK - 1))) {
            atomicOr(&rowMaskS, 1u << d2);
            int e = atomicAdd(&evn[d2], 1);
            if (e < EVCAP) ev[d2][e] = make_uint2(xp, __float_as_uint(-hc));
            else           atomicOr(&ovMaskS, 1u << d2);
        }
    }
    __syncthreads();
    const unsigned rowMask = rowMaskS;
    const unsigned ovMask  = ovMaskS;

    const int y0 = rowBase + warp * CHUNK;
    float4* row4 = rows4[warp];
    float*  row  = (float*)row4;

    // ---- zero the build row (STS.128, conflict-free) ----
    #pragma unroll
    for (int i = lane; i < ROW_V4; i += 32)
        row4[i] = make_float4(0.f, 0.f, 0.f, 0.f);
    __syncwarp();

    // ---- scatter boxes active at y0 (no x2 guard: word 640 never read) ----
    #pragma unroll
    for (int i = lane; i < NBOX; i += 32) {
        uint2 bx = sbox[i];
        int y1 = (int)(bx.y & 0xFFFF), y2 = (int)(bx.y >> 16);
        if (y1 <= y0 && y0 < y2) {
            float hc = sc[i];
            atomicAdd(&row[padw((int)(bx.x & 0xFFFF))],  hc);
            atomicAdd(&row[padw((int)(bx.x >> 16))],    -hc);
        }
    }
    __syncwarp();

    // ---- scan first row into registers (4x LDS.128, stride 80B: conflict-free) ----
    float v[16];
    {
        const int base4 = lane * 5;            // word 20*lane
        float4 f[4];
        #pragma unroll
        for (int k = 0; k < 4; k++) f[k] = row4[base4 + k];
        const float* fs = (const float*)f;
        float run = 0.0f;
        #pragma unroll
        for (int j = 0; j < 16; j++) { run += fs[j]; v[j] = run; }

        float x = run;
        #pragma unroll
        for (int o = 1; o < 32; o <<= 1) {
            float t = __shfl_up_sync(0xFFFFFFFFu, x, o);
            if (lane >= o) x += t;
        }
        float pre = __shfl_up_sync(0xFFFFFFFFu, x, 1);
        if (lane == 0) pre = 0.0f;
        #pragma unroll
        for (int j = 0; j < 16; j++) v[j] += pre;
    }

    // ---- per-row: sigmoid + store, then apply next row's events ----
    const int s = lane * 16;
    float* dstBase = out + (((size_t)b * FEAT + y0) * FEAT) + s;

    for (int r = 0; r < CHUNK; r++) {
        // sigmoid(2v) = 0.5*tanh(v)+0.5 ; compute+store 4 at a time
        float4* dst = (float4*)(dstBase + (size_t)r * FEAT);
        #pragma unroll
        for (int g = 0; g < 4; g++) {
            float4 t4;
            float* tp = (float*)&t4;
            #pragma unroll
            for (int j = 0; j < 4; j++) {
                float t;
                asm("tanh.approx.f32 %0, %1;" : "=f"(t) : "f"(v[g * 4 + j]));
                tp[j] = fmaf(0.5f, t, 0.5f);
            }
            dst[g] = t4;
        }

        if (r + 1 < CHUNK) {
            const int target = warp * CHUNK + r + 1;      // block-row index
            if ((rowMask >> target) & 1u) {
                if (!((ovMask >> target) & 1u)) {
                    // fast path: broadcast-read bucket events (no shfl/ballot)
                    const int n = evn[target];
                    for (int k = 0; k < n; k++) {
                        uint2 e = ev[target][k];
                        int lo = max((int)(e.x & 0x3FF) - s, 0);
                        int hi = min((int)((e.x >> 10) & 0x3FF) - s, 16);
                        float c2 = __uint_as_float(e.y);
                        if (lo < hi) {
                            #pragma unroll
                            for (int j = 0; j < 16; j++)
                                if (j >= lo && j < hi) v[j] += c2;
                        }
                    }
                } else {
                    // rare overflow: broadcast rescan of full box list
                    const int yt = y0 + r + 1;
                    for (int i = 0; i < NBOX; i++) {
                        uint2 bx = sbox[i];
                        int y1 = (int)(bx.y & 0xFFFF), y2 = (int)(bx.y >> 16);
                        bool en = (y1 == yt), ex = (y2 == yt && y2 > y1);
                        if (en || ex) {
                            float c2 = en ? sc[i] : -sc[i];
                            int lo = max((int)(bx.x & 0xFFFF) - s, 0);
                            int hi = min((int)(bx.x >> 16) - s, 16);
                            if (lo < hi) {
                                #pragma unroll
                                for (int j = 0; j < 16; j++)
                                    if (j >= lo && j < hi) v[j] += c2;
                            }
                        }
                    }
                }
            }
        }
    }
}

extern "C" void kernel_launch(void* const* d_in, const int* in_sizes, int n_in,
                              void* d_out, int out_size)
{
    const float* preds = (const float*)d_in[0];
    float* out = (float*)d_out;

    int B = in_sizes[0] / (NBOX * 5);               // 64 for bench shapes
    int blocksPerBatch = FEAT / ROWS_PER_BLOCK;     // 16
    dim3 grid(B * blocksPerBatch);                  // 1024
    dim3 block(128);
    bbox_att_kernel<<<grid, block>>>(preds, out, blocksPerBatch);
}